// round 6
// baseline (speedup 1.0000x reference)
#include <cuda_runtime.h>
#include <cuda_bf16.h>
#include <cstddef>

#define DD 128
#define MAXN 100000
#define MAXE 1000000
#define APAD 132   // smem row stride: %4==0 (16B-aligned rows), and (4*m+k) covers banks 0..31 for frags

// ---- scratch (no cudaMalloc allowed) ----
__device__ float g_aggr[(size_t)MAXN * DD];
__device__ float g_z1[(size_t)MAXN * DD];
__device__ float g_z2[(size_t)MAXN * DD];
__device__ int   g_idx[(size_t)2 * MAXE];
__device__ int   g_fmt;
__device__ float g_sum[DD];
__device__ float g_sq[DD];
__device__ float g_s1[DD];
__device__ float g_c1[DD];
__device__ float g_sh[DD];
__device__ float g_ch[DD];

// ---------------------------------------------------------------- edge fmt detect (parallel)
__global__ void detect_kernel(const int* __restrict__ ei32, int E) {
    __shared__ int bad;
    if (threadIdx.x == 0) bad = 0;
    __syncthreads();
    long long e = (long long)(threadIdx.x + 1) * (2LL * E) / 66;
    if (ei32[2 * (e >> 1) + 1] != 0) bad = 1;
    __syncthreads();
    if (threadIdx.x == 0) g_fmt = !bad;
}

__global__ void convert_kernel(const void* __restrict__ ei, int n2, int N) {
    int i = blockIdx.x * blockDim.x + threadIdx.x;
    if (i >= n2) return;
    int v;
    if (g_fmt) v = (int)((const long long*)ei)[i];
    else       v = ((const int*)ei)[i];
    if (v < 0) v = 0;
    if (v >= N) v = N - 1;
    g_idx[i] = v;
}

// ---------------------------------------------------------------- aggr init
__global__ void init_kernel(const float4* __restrict__ h, float4* __restrict__ aggr,
                            const float* __restrict__ s, const float* __restrict__ c,
                            const float* __restrict__ epsP, int layer, int mode, int n4) {
    int i = blockIdx.x * blockDim.x + threadIdx.x;
    if (i >= n4) return;
    float ev = 1.0f + epsP[layer];
    float4 v = h[i];
    if (mode) {
        int k = (i & 31) * 4;
        v.x = fmaxf(fmaf(s[k + 0], v.x, c[k + 0]), 0.f);
        v.y = fmaxf(fmaf(s[k + 1], v.y, c[k + 1]), 0.f);
        v.z = fmaxf(fmaf(s[k + 2], v.z, c[k + 2]), 0.f);
        v.w = fmaxf(fmaf(s[k + 3], v.w, c[k + 3]), 0.f);
    }
    aggr[i] = make_float4(ev * v.x, ev * v.y, ev * v.z, ev * v.w);
}

// ---------------------------------------------------------------- scatter (red.global.v4)
__global__ void scatter_kernel(const float4* __restrict__ h,
                               const int* __restrict__ idx, int E,
                               float* __restrict__ aggr,
                               const float* __restrict__ sH,
                               const float* __restrict__ cH, int mode) {
    __shared__ float ss[DD], sc[DD];
    if (mode) {
        if (threadIdx.x < DD) { ss[threadIdx.x] = sH[threadIdx.x]; sc[threadIdx.x] = cH[threadIdx.x]; }
        __syncthreads();
    }
    int gt = blockIdx.x * blockDim.x + threadIdx.x;
    int e = gt >> 5;
    if (e >= E) return;
    int lane = gt & 31;
    int src = idx[e];
    int dst = idx[E + e];
    float4 v = h[(size_t)src * 32 + lane];
    int k = lane * 4;
    if (mode) {
        v.x = fmaf(ss[k + 0], v.x, sc[k + 0]);
        v.y = fmaf(ss[k + 1], v.y, sc[k + 1]);
        v.z = fmaf(ss[k + 2], v.z, sc[k + 2]);
        v.w = fmaf(ss[k + 3], v.w, sc[k + 3]);
    }
    v.x = fmaxf(v.x, 0.f); v.y = fmaxf(v.y, 0.f);
    v.z = fmaxf(v.z, 0.f); v.w = fmaxf(v.w, 0.f);
    if (v.x != 0.f || v.y != 0.f || v.z != 0.f || v.w != 0.f) {
        float* o = aggr + (size_t)dst * DD + k;
        asm volatile("red.global.add.v4.f32 [%0], {%1, %2, %3, %4};"
                     :: "l"(o), "f"(v.x), "f"(v.y), "f"(v.z), "f"(v.w) : "memory");
    }
}

// ---------------------------------------------------------------- 3xTF32 GEMM helpers
__device__ __forceinline__ unsigned f2tf(float x) {
    unsigned r;
    asm("cvt.rna.tf32.f32 %0, %1;" : "=r"(r) : "f"(x));
    return r;
}
__device__ __forceinline__ void mma8(float* c, unsigned a0, unsigned a1, unsigned a2, unsigned a3,
                                     unsigned b0, unsigned b1) {
    asm volatile(
        "mma.sync.aligned.m16n8k8.row.col.f32.tf32.tf32.f32 "
        "{%0,%1,%2,%3},{%4,%5,%6,%7},{%8,%9},{%0,%1,%2,%3};"
        : "+f"(c[0]), "+f"(c[1]), "+f"(c[2]), "+f"(c[3])
        : "r"(a0), "r"(a1), "r"(a2), "r"(a3), "r"(b0), "r"(b1));
}

// ---------------------------------------------------------------- GEMM (3xTF32 tensor core)
// out[row][j] = sum_k a(row,k) * W[j][k] + bias[j]
// mode 0: a = Ab (aggr holds (1+eps)h + msgs);  mode 2: a = relu(sIn*Ab+cIn)
// Epilogue: write Z, accumulate per-feature sum & sumsq into gsum/gsq.
__global__ void __launch_bounds__(256, 1) gemm_tf32(
    const float* __restrict__ Ab,
    const float* __restrict__ W, const float* __restrict__ bias,
    const float* __restrict__ sIn, const float* __restrict__ cIn,
    int mode, int M,
    float* __restrict__ Z, float* __restrict__ gsum, float* __restrict__ gsq) {
    extern __shared__ float sm[];
    float* As = sm;                 // [row][k] 128 x APAD
    float* Ws = As + 128 * APAD;    // [n][k]   128 x APAD
    float* csum = Ws + 128 * APAD;  // 128
    float* csq = csum + DD;         // 128

    const int tid = threadIdx.x;
    const int lane = tid & 31, wid = tid >> 5;
    const int rowBase = blockIdx.x << 7;

    if (tid < DD) { csum[tid] = 0.f; csq[tid] = 0.f; }

    // W -> Ws[n][k] (coalesced load, conflict-free store)
    for (int t = 0; t < 64; t++) {
        int i = tid + t * 256;
        int n = i >> 7, k = i & 127;
        Ws[n * APAD + k] = W[i];
    }
    // A -> As[row][k], fused pre-op
    for (int t = 0; t < 16; t++) {
        int i = tid + t * 256;           // 4096 float4
        int row = i >> 5, kq = (i & 31) * 4;
        float4 v = make_float4(0.f, 0.f, 0.f, 0.f);
        int gr = rowBase + row;
        if (gr < M) {
            v = *(const float4*)(Ab + (size_t)gr * DD + kq);
            if (mode == 2) {
                v.x = fmaxf(fmaf(sIn[kq + 0], v.x, cIn[kq + 0]), 0.f);
                v.y = fmaxf(fmaf(sIn[kq + 1], v.y, cIn[kq + 1]), 0.f);
                v.z = fmaxf(fmaf(sIn[kq + 2], v.z, cIn[kq + 2]), 0.f);
                v.w = fmaxf(fmaf(sIn[kq + 3], v.w, cIn[kq + 3]), 0.f);
            }
        }
        *(float4*)(As + row * APAD + kq) = v;
    }
    __syncthreads();

    const int q = lane & 3, mr = lane >> 2;
    const int mw = wid * 16;             // 16 rows per warp

    float acc[16][4];
#pragma unroll
    for (int nt = 0; nt < 16; nt++)
#pragma unroll
        for (int j = 0; j < 4; j++) acc[nt][j] = 0.f;

    for (int kt = 0; kt < 16; kt++) {
        const int k0 = kt * 8;
        const float* ap = As + (mw + mr) * APAD + k0 + q;
        float a0 = ap[0], a1 = ap[8 * APAD], a2 = ap[4], a3 = ap[8 * APAD + 4];
        unsigned aH0 = f2tf(a0), aH1 = f2tf(a1), aH2 = f2tf(a2), aH3 = f2tf(a3);
        unsigned aL0 = __float_as_uint(a0 - __uint_as_float(aH0));
        unsigned aL1 = __float_as_uint(a1 - __uint_as_float(aH1));
        unsigned aL2 = __float_as_uint(a2 - __uint_as_float(aH2));
        unsigned aL3 = __float_as_uint(a3 - __uint_as_float(aH3));
#pragma unroll
        for (int nt = 0; nt < 16; nt++) {
            const float* bp = Ws + (nt * 8 + mr) * APAD + k0 + q;
            float b0 = bp[0], b1 = bp[4];
            unsigned bH0 = f2tf(b0), bH1 = f2tf(b1);
            unsigned bL0 = __float_as_uint(b0 - __uint_as_float(bH0));
            unsigned bL1 = __float_as_uint(b1 - __uint_as_float(bH1));
            mma8(acc[nt], aH0, aH1, aH2, aH3, bH0, bH1);
            mma8(acc[nt], aL0, aL1, aL2, aL3, bH0, bH1);
            mma8(acc[nt], aH0, aH1, aH2, aH3, bL0, bL1);
        }
    }

    // epilogue: bias, store Z, per-feature stats
    const int r0 = rowBase + mw + mr;
    const int r1 = r0 + 8;
#pragma unroll
    for (int nt = 0; nt < 16; nt++) {
        int j0 = nt * 8 + 2 * q;
        float bx = bias[j0], by = bias[j0 + 1];
        float v00 = acc[nt][0] + bx, v01 = acc[nt][1] + by;
        float v10 = acc[nt][2] + bx, v11 = acc[nt][3] + by;
        bool ok0 = r0 < M, ok1 = r1 < M;
        if (ok0) *(float2*)(Z + (size_t)r0 * DD + j0) = make_float2(v00, v01);
        if (ok1) *(float2*)(Z + (size_t)r1 * DD + j0) = make_float2(v10, v11);
        float s0 = (ok0 ? v00 : 0.f) + (ok1 ? v10 : 0.f);
        float s1 = (ok0 ? v01 : 0.f) + (ok1 ? v11 : 0.f);
        float q0 = (ok0 ? v00 * v00 : 0.f) + (ok1 ? v10 * v10 : 0.f);
        float q1 = (ok0 ? v01 * v01 : 0.f) + (ok1 ? v11 * v11 : 0.f);
#pragma unroll
        for (int m = 4; m <= 16; m <<= 1) {
            s0 += __shfl_xor_sync(0xffffffff, s0, m);
            s1 += __shfl_xor_sync(0xffffffff, s1, m);
            q0 += __shfl_xor_sync(0xffffffff, q0, m);
            q1 += __shfl_xor_sync(0xffffffff, q1, m);
        }
        if (mr == 0) {
            atomicAdd(&csum[j0], s0);
            atomicAdd(&csum[j0 + 1], s1);
            atomicAdd(&csq[j0], q0);
            atomicAdd(&csq[j0 + 1], q1);
        }
    }
    __syncthreads();
    if (tid < DD) {
        atomicAdd(&gsum[tid], csum[tid]);
        atomicAdd(&gsq[tid], csq[tid]);
    }
}

// ---------------------------------------------------------------- BN finalize
__global__ void finalize_kernel(float* __restrict__ gsum, float* __restrict__ gsq,
                                const float* __restrict__ gamma, const float* __restrict__ beta,
                                float invM, float* __restrict__ sOut, float* __restrict__ cOut) {
    int j = threadIdx.x;
    float mean = gsum[j] * invM;
    float var = gsq[j] * invM - mean * mean;
    float s = gamma[j] * rsqrtf(var + 1e-5f);
    sOut[j] = s;
    cOut[j] = beta[j] - mean * s;
    gsum[j] = 0.f;
    gsq[j] = 0.f;
}

// ---------------------------------------------------------------- final apply
__global__ void apply_kernel(const float4* __restrict__ z, const float* __restrict__ s,
                             const float* __restrict__ c, float4* __restrict__ out, int n4) {
    int i = blockIdx.x * blockDim.x + threadIdx.x;
    if (i >= n4) return;
    int k = (i & 31) * 4;
    float4 v = z[i];
    out[i] = make_float4(fmaf(s[k + 0], v.x, c[k + 0]),
                         fmaf(s[k + 1], v.y, c[k + 1]),
                         fmaf(s[k + 2], v.z, c[k + 2]),
                         fmaf(s[k + 3], v.w, c[k + 3]));
}

// ---------------------------------------------------------------- launch
extern "C" void kernel_launch(void* const* d_in, const int* in_sizes, int n_in,
                              void* d_out, int out_size) {
    const float* x    = (const float*)d_in[0];
    const void*  ei   = d_in[1];
    const float* W1   = (const float*)d_in[2];
    const float* b1   = (const float*)d_in[3];
    const float* g1   = (const float*)d_in[4];
    const float* bt1  = (const float*)d_in[5];
    const float* W2   = (const float*)d_in[6];
    const float* b2   = (const float*)d_in[7];
    const float* epsv = (const float*)d_in[8];
    const float* gout = (const float*)d_in[9];
    const float* bout = (const float*)d_in[10];

    int N = in_sizes[0] / DD;
    int E = in_sizes[1] / 2;

    void* p;
    cudaGetSymbolAddress(&p, g_aggr); float* aggr = (float*)p;
    cudaGetSymbolAddress(&p, g_z1);   float* z1   = (float*)p;
    cudaGetSymbolAddress(&p, g_z2);   float* z2   = (float*)p;
    cudaGetSymbolAddress(&p, g_idx);  int*   idx  = (int*)p;
    cudaGetSymbolAddress(&p, g_sum);  float* gsum = (float*)p;
    cudaGetSymbolAddress(&p, g_sq);   float* gsq  = (float*)p;
    cudaGetSymbolAddress(&p, g_s1);   float* s1   = (float*)p;
    cudaGetSymbolAddress(&p, g_c1);   float* c1   = (float*)p;
    cudaGetSymbolAddress(&p, g_sh);   float* sh   = (float*)p;
    cudaGetSymbolAddress(&p, g_ch);   float* ch   = (float*)p;

    constexpr int SMEM = (2 * 128 * APAD + 2 * DD) * 4;
    cudaFuncSetAttribute(gemm_tf32, cudaFuncAttributeMaxDynamicSharedMemorySize, SMEM);

    float invM = 1.0f / (float)N;
    int n4 = N * (DD / 4);
    int zb = (n4 + 255) / 256;
    long long sthreads = (long long)E * 32;
    int sb = (int)((sthreads + 255) / 256);
    int gb = (N + 127) / 128;
    int n2 = 2 * E;
    int cb = (n2 + 255) / 256;

    detect_kernel<<<1, 64>>>((const int*)ei, E);
    convert_kernel<<<cb, 256>>>(ei, n2, N);

    // ---- layer 0 ----
    init_kernel<<<zb, 256>>>((const float4*)x, (float4*)aggr, nullptr, nullptr, epsv, 0, 0, n4);
    scatter_kernel<<<sb, 256>>>((const float4*)x, idx, E, aggr, nullptr, nullptr, 0);
    gemm_tf32<<<gb, 256, SMEM>>>(aggr, W1, b1, nullptr, nullptr, 0, N, z1, gsum, gsq);
    finalize_kernel<<<1, DD>>>(gsum, gsq, g1, bt1, invM, s1, c1);
    gemm_tf32<<<gb, 256, SMEM>>>(z1, W2, b2, s1, c1, 2, N, z2, gsum, gsq);
    finalize_kernel<<<1, DD>>>(gsum, gsq, gout, bout, invM, sh, ch);

    // ---- layer 1 ----
    init_kernel<<<zb, 256>>>((const float4*)z2, (float4*)aggr, sh, ch, epsv, 1, 1, n4);
    scatter_kernel<<<sb, 256>>>((const float4*)z2, idx, E, aggr, sh, ch, 1);
    gemm_tf32<<<gb, 256, SMEM>>>(aggr, W1 + DD * DD, b1 + DD, nullptr, nullptr, 0, N, z1, gsum, gsq);
    finalize_kernel<<<1, DD>>>(gsum, gsq, g1 + DD, bt1 + DD, invM, s1, c1);
    gemm_tf32<<<gb, 256, SMEM>>>(z1, W2 + DD * DD, b2 + DD, s1, c1, 2, N, z2, gsum, gsq);
    finalize_kernel<<<1, DD>>>(gsum, gsq, gout + DD, bout + DD, invM, sh, ch);

    apply_kernel<<<zb, 256>>>((const float4*)z2, sh, ch, (float4*)d_out, n4);
}